// round 11
// baseline (speedup 1.0000x reference)
#include <cuda_runtime.h>
#include <cuda_bf16.h>

// MultiHashtable4d: 16-level 4D hash-grid encode.
//   out[n, l*2 + c] = sum_{16 corners} w_corner * data[l, index(corner), c]
// Levels with prod(entrys_num[l]) > T use the spatial hash
//   (x ^ y*19349663 ^ z*83492791 ^ w*73856093) % T,
// earlier levels the direct row-major index. Indices clamped per-dim.
//
// Bit-exactness notes vs the JAX reference:
//  * the "+1" corner is trunc(fp32(f + 1.0f)) -- the fp32 add can round UP
//    across an integer boundary for large f, selecting floor+2. We replicate
//    that exactly (this was the rel_err=1.4e-3 bug).
//  * divisions use __fdiv_rn so compiler fast-math flags can't perturb f.
//
// entrys_num dtype is sniffed at runtime (int64 storage has zero hi-words).
// Layout: thread = (point n, level l), l fastest -> coalesced float2 stores;
// 16 corner gathers batched per thread (MLP=16). 64-bit mod via Barrett.

#define LVL 16

__global__ void __launch_bounds__(256) mh4d_kernel(
    const float* __restrict__ xyz,         // [N,3]
    const float* __restrict__ tt,          // [N,1]
    const float2* __restrict__ data,       // [L,T] of float2 (f=2)
    const float* __restrict__ bounds,      // [2,4]
    const float* __restrict__ es,          // [L,4] entrys_size (f32)
    const int*   __restrict__ en_raw,      // [L,4] entrys_num (i32 or i64 storage)
    float2* __restrict__ out,              // [N,L] of float2
    int N, unsigned Tsz, unsigned long long magic)
{
    __shared__ float s_es[LVL * 4];
    __shared__ int   s_en[LVL * 4];
    __shared__ int   s_hash[LVL];
    __shared__ float s_b0[4];
    __shared__ int   s_is64;

    const int tid = threadIdx.x;
    if (tid == 0) {
        // entrys_num[0] = [16,16,16,100]; int64 storage viewed as i32 is
        // 16,0,16,0,... -> odd words zero iff int64. Reads stay in-bounds
        // for either layout.
        s_is64 = (en_raw[1] == 0 && en_raw[3] == 0 &&
                  en_raw[5] == 0 && en_raw[7] == 0) ? 1 : 0;
    }
    if (tid < LVL * 4) s_es[tid] = es[tid];
    if (tid < 4)       s_b0[tid] = bounds[tid];
    __syncthreads();
    if (tid < LVL * 4) s_en[tid] = s_is64 ? en_raw[2 * tid] : en_raw[tid];
    __syncthreads();
    if (tid == 0) {
        // first level with prod(entrys_num) > T starts hashing; prefix-OR
        // reproduces the reference's break semantics.
        int acc = 0;
        #pragma unroll
        for (int i = 0; i < LVL; i++) {
            long long p = (long long)s_en[4*i+0] * s_en[4*i+1]
                        * s_en[4*i+2] * s_en[4*i+3];
            acc |= (p > (long long)Tsz) ? 1 : 0;
            s_hash[i] = acc;
        }
    }
    __syncthreads();

    const int gid = blockIdx.x * 256 + tid;
    const int n = gid >> 4;
    const int l = gid & 15;
    if (n >= N) return;

    const float px = xyz[3 * n + 0];
    const float py = xyz[3 * n + 1];
    const float pz = xyz[3 * n + 2];
    // t -= start_frame/(total_frame-1); bounds[0][3] = start_frame/total_frame
    // -> shift = b0w * nt/(nt-1), nt = total_frame = en[0][3]. (=0 here.)
    const float nt = (float)s_en[3];
    const float pw = tt[n] - __fdiv_rn(s_b0[3] * nt, nt - 1.0f);

    const float fx = __fdiv_rn(px - s_b0[0], s_es[4 * l + 0]);
    const float fy = __fdiv_rn(py - s_b0[1], s_es[4 * l + 1]);
    const float fz = __fdiv_rn(pz - s_b0[2], s_es[4 * l + 2]);
    const float fw = __fdiv_rn(pw - s_b0[3], s_es[4 * l + 3]);

    // low corner: trunc(f) (coords >= 0 inside bbox, trunc == astype)
    const int bx = (int)fx, by = (int)fy, bz = (int)fz, bw = (int)fw;
    // high corner: trunc(fp32(f + 1.0f)) -- NOT bx+1; the fp32 add may round
    // up across an integer boundary (matches reference astype semantics).
    const int hx = (int)__fadd_rn(fx, 1.0f);
    const int hy = (int)__fadd_rn(fy, 1.0f);
    const int hz = (int)__fadd_rn(fz, 1.0f);
    const int hw = (int)__fadd_rn(fw, 1.0f);

    const float ox = fx - (float)bx;
    const float oy = fy - (float)by;
    const float oz = fz - (float)bz;
    const float ow = fw - (float)bw;

    const int en0 = s_en[4 * l + 0];
    const int en1 = s_en[4 * l + 1];
    const int en2 = s_en[4 * l + 2];
    const int en3 = s_en[4 * l + 3];

    int cxs[2], cys[2], czs[2], cws[2];
    cxs[0] = min(max(bx, 0), en0 - 1);  cxs[1] = min(max(hx, 0), en0 - 1);
    cys[0] = min(max(by, 0), en1 - 1);  cys[1] = min(max(hy, 0), en1 - 1);
    czs[0] = min(max(bz, 0), en2 - 1);  czs[1] = min(max(hz, 0), en2 - 1);
    cws[0] = min(max(bw, 0), en3 - 1);  cws[1] = min(max(hw, 0), en3 - 1);

    float wxs[2], wys[2], wzs[2], wws[2];
    wxs[0] = __saturatef(1.0f - ox); wxs[1] = __saturatef(ox);
    wys[0] = __saturatef(1.0f - oy); wys[1] = __saturatef(oy);
    wzs[0] = __saturatef(1.0f - oz); wzs[1] = __saturatef(oz);
    wws[0] = __saturatef(1.0f - ow); wws[1] = __saturatef(ow);

    const bool ish = (s_hash[l] != 0);
    const float2* tab = data + (size_t)Tsz * (unsigned)l;

    // Phase 1: all 16 indices, all 16 gathers in flight (MLP=16)
    float2 vals[16];
    #pragma unroll
    for (int i = 0; i < 16; i++) {
        const int X = cxs[(i >> 3) & 1];
        const int Y = cys[(i >> 2) & 1];
        const int Z = czs[(i >> 1) & 1];
        const int W = cws[i & 1];

        // direct row-major index: fits u32 for direct levels (prod <= T)
        unsigned direct = ((unsigned)X * (unsigned)en1 + (unsigned)Y);
        direct = (direct * (unsigned)en2 + (unsigned)Z);
        direct = direct * (unsigned)en3 + (unsigned)W;

        // spatial hash (operands non-negative)
        unsigned long long h =
              (unsigned long long)(unsigned)X
            ^ ((unsigned long long)(unsigned)Y * 19349663ull)
            ^ ((unsigned long long)(unsigned)Z * 83492791ull)
            ^ ((unsigned long long)(unsigned)W * 73856093ull);
        // Barrett: magic = floor((2^64-1)/Tsz); h < 2^39 -> one subtract
        // suffices, two kept for safety.
        unsigned long long q = __umul64hi(h, magic);
        unsigned long long r = h - q * (unsigned long long)Tsz;
        if (r >= (unsigned long long)Tsz) r -= (unsigned long long)Tsz;
        if (r >= (unsigned long long)Tsz) r -= (unsigned long long)Tsz;

        const unsigned idx = ish ? (unsigned)r : direct;
        vals[i] = __ldg(&tab[idx]);
    }

    // Phase 2: weighted accumulation (corner order matches reference sum)
    float acc0 = 0.0f, acc1 = 0.0f;
    #pragma unroll
    for (int i = 0; i < 16; i++) {
        const float w = wxs[(i >> 3) & 1] * wys[(i >> 2) & 1]
                      * wzs[(i >> 1) & 1] * wws[i & 1];
        acc0 += w * vals[i].x;
        acc1 += w * vals[i].y;
    }

    out[(size_t)n * 16 + l] = make_float2(acc0, acc1);
}

extern "C" void kernel_launch(void* const* d_in, const int* in_sizes, int n_in,
                              void* d_out, int out_size) {
    const float*  xyz    = (const float*)d_in[0];
    const float*  tt     = (const float*)d_in[1];
    const float2* data   = (const float2*)d_in[2];
    const float*  bounds = (const float*)d_in[3];
    // d_in[4] (offsets) is the fixed 16x4 binary corner table -> hard-coded
    const float*  es     = (const float*)d_in[5];
    const int*    en     = (const int*)d_in[6];
    // d_in[7..9]: start_hash / start_frame / total_frame -> derived on device

    const int N = in_sizes[0] / 3;                        // xyz is [N,3]
    const int LF = out_size / N;                          // = L*f = 32
    const unsigned Tsz = (unsigned)(in_sizes[2] / LF);    // data is [L,T,f]
    const unsigned long long magic = 0xFFFFFFFFFFFFFFFFull / (unsigned long long)Tsz;

    const int total = N * 16;
    const int blocks = (total + 255) / 256;
    mh4d_kernel<<<blocks, 256>>>(xyz, tt, data, bounds, es, en,
                                 (float2*)d_out, N, Tsz, magic);
}

// round 12
// speedup vs baseline: 1.0027x; 1.0027x over previous
#include <cuda_runtime.h>
#include <cuda_bf16.h>

// MultiHashtable4d: 16-level 4D hash-grid encode.
//   out[n, l*2 + c] = sum_{16 corners} w_corner * data[l, index(corner), c]
// Levels with prod(entrys_num[l]) > T use the spatial hash
//   (x ^ y*19349663 ^ z*83492791 ^ w*73856093) % T,
// earlier levels the direct row-major index. Indices clamped per-dim.
//
// Bit-exactness notes vs the JAX reference:
//  * the "+1" corner is trunc(fp32(f + 1.0f)) -- the fp32 add can round UP
//    across an integer boundary for large f, selecting floor+2. We replicate
//    that exactly (this was the rel_err=1.4e-3 bug).
//  * divisions use __fdiv_rn so compiler fast-math flags can't perturb f.
//
// entrys_num dtype is sniffed at runtime (int64 storage has zero hi-words).
// Layout: thread = (point n, level l), l fastest -> coalesced float2 stores;
// 16 corner gathers batched per thread (MLP=16). 64-bit mod via Barrett.

#define LVL 16

__global__ void __launch_bounds__(256) mh4d_kernel(
    const float* __restrict__ xyz,         // [N,3]
    const float* __restrict__ tt,          // [N,1]
    const float2* __restrict__ data,       // [L,T] of float2 (f=2)
    const float* __restrict__ bounds,      // [2,4]
    const float* __restrict__ es,          // [L,4] entrys_size (f32)
    const int*   __restrict__ en_raw,      // [L,4] entrys_num (i32 or i64 storage)
    float2* __restrict__ out,              // [N,L] of float2
    int N, unsigned Tsz, unsigned long long magic)
{
    __shared__ float s_es[LVL * 4];
    __shared__ int   s_en[LVL * 4];
    __shared__ int   s_hash[LVL];
    __shared__ float s_b0[4];
    __shared__ int   s_is64;

    const int tid = threadIdx.x;
    if (tid == 0) {
        // entrys_num[0] = [16,16,16,100]; int64 storage viewed as i32 is
        // 16,0,16,0,... -> odd words zero iff int64. Reads stay in-bounds
        // for either layout.
        s_is64 = (en_raw[1] == 0 && en_raw[3] == 0 &&
                  en_raw[5] == 0 && en_raw[7] == 0) ? 1 : 0;
    }
    if (tid < LVL * 4) s_es[tid] = es[tid];
    if (tid < 4)       s_b0[tid] = bounds[tid];
    __syncthreads();
    if (tid < LVL * 4) s_en[tid] = s_is64 ? en_raw[2 * tid] : en_raw[tid];
    __syncthreads();
    if (tid == 0) {
        // first level with prod(entrys_num) > T starts hashing; prefix-OR
        // reproduces the reference's break semantics.
        int acc = 0;
        #pragma unroll
        for (int i = 0; i < LVL; i++) {
            long long p = (long long)s_en[4*i+0] * s_en[4*i+1]
                        * s_en[4*i+2] * s_en[4*i+3];
            acc |= (p > (long long)Tsz) ? 1 : 0;
            s_hash[i] = acc;
        }
    }
    __syncthreads();

    const int gid = blockIdx.x * 256 + tid;
    const int n = gid >> 4;
    const int l = gid & 15;
    if (n >= N) return;

    const float px = xyz[3 * n + 0];
    const float py = xyz[3 * n + 1];
    const float pz = xyz[3 * n + 2];
    // t -= start_frame/(total_frame-1); bounds[0][3] = start_frame/total_frame
    // -> shift = b0w * nt/(nt-1), nt = total_frame = en[0][3]. (=0 here.)
    const float nt = (float)s_en[3];
    const float pw = tt[n] - __fdiv_rn(s_b0[3] * nt, nt - 1.0f);

    const float fx = __fdiv_rn(px - s_b0[0], s_es[4 * l + 0]);
    const float fy = __fdiv_rn(py - s_b0[1], s_es[4 * l + 1]);
    const float fz = __fdiv_rn(pz - s_b0[2], s_es[4 * l + 2]);
    const float fw = __fdiv_rn(pw - s_b0[3], s_es[4 * l + 3]);

    // low corner: trunc(f) (coords >= 0 inside bbox, trunc == astype)
    const int bx = (int)fx, by = (int)fy, bz = (int)fz, bw = (int)fw;
    // high corner: trunc(fp32(f + 1.0f)) -- NOT bx+1; the fp32 add may round
    // up across an integer boundary (matches reference astype semantics).
    const int hx = (int)__fadd_rn(fx, 1.0f);
    const int hy = (int)__fadd_rn(fy, 1.0f);
    const int hz = (int)__fadd_rn(fz, 1.0f);
    const int hw = (int)__fadd_rn(fw, 1.0f);

    const float ox = fx - (float)bx;
    const float oy = fy - (float)by;
    const float oz = fz - (float)bz;
    const float ow = fw - (float)bw;

    const int en0 = s_en[4 * l + 0];
    const int en1 = s_en[4 * l + 1];
    const int en2 = s_en[4 * l + 2];
    const int en3 = s_en[4 * l + 3];

    int cxs[2], cys[2], czs[2], cws[2];
    cxs[0] = min(max(bx, 0), en0 - 1);  cxs[1] = min(max(hx, 0), en0 - 1);
    cys[0] = min(max(by, 0), en1 - 1);  cys[1] = min(max(hy, 0), en1 - 1);
    czs[0] = min(max(bz, 0), en2 - 1);  czs[1] = min(max(hz, 0), en2 - 1);
    cws[0] = min(max(bw, 0), en3 - 1);  cws[1] = min(max(hw, 0), en3 - 1);

    float wxs[2], wys[2], wzs[2], wws[2];
    wxs[0] = __saturatef(1.0f - ox); wxs[1] = __saturatef(ox);
    wys[0] = __saturatef(1.0f - oy); wys[1] = __saturatef(oy);
    wzs[0] = __saturatef(1.0f - oz); wzs[1] = __saturatef(oz);
    wws[0] = __saturatef(1.0f - ow); wws[1] = __saturatef(ow);

    const bool ish = (s_hash[l] != 0);
    const float2* tab = data + (size_t)Tsz * (unsigned)l;

    // Phase 1: all 16 indices, all 16 gathers in flight (MLP=16)
    float2 vals[16];
    #pragma unroll
    for (int i = 0; i < 16; i++) {
        const int X = cxs[(i >> 3) & 1];
        const int Y = cys[(i >> 2) & 1];
        const int Z = czs[(i >> 1) & 1];
        const int W = cws[i & 1];

        // direct row-major index: fits u32 for direct levels (prod <= T)
        unsigned direct = ((unsigned)X * (unsigned)en1 + (unsigned)Y);
        direct = (direct * (unsigned)en2 + (unsigned)Z);
        direct = direct * (unsigned)en3 + (unsigned)W;

        // spatial hash (operands non-negative)
        unsigned long long h =
              (unsigned long long)(unsigned)X
            ^ ((unsigned long long)(unsigned)Y * 19349663ull)
            ^ ((unsigned long long)(unsigned)Z * 83492791ull)
            ^ ((unsigned long long)(unsigned)W * 73856093ull);
        // Barrett: magic = floor((2^64-1)/Tsz); h < 2^39 -> one subtract
        // suffices, two kept for safety.
        unsigned long long q = __umul64hi(h, magic);
        unsigned long long r = h - q * (unsigned long long)Tsz;
        if (r >= (unsigned long long)Tsz) r -= (unsigned long long)Tsz;
        if (r >= (unsigned long long)Tsz) r -= (unsigned long long)Tsz;

        const unsigned idx = ish ? (unsigned)r : direct;
        vals[i] = __ldg(&tab[idx]);
    }

    // Phase 2: weighted accumulation (corner order matches reference sum)
    float acc0 = 0.0f, acc1 = 0.0f;
    #pragma unroll
    for (int i = 0; i < 16; i++) {
        const float w = wxs[(i >> 3) & 1] * wys[(i >> 2) & 1]
                      * wzs[(i >> 1) & 1] * wws[i & 1];
        acc0 += w * vals[i].x;
        acc1 += w * vals[i].y;
    }

    out[(size_t)n * 16 + l] = make_float2(acc0, acc1);
}

extern "C" void kernel_launch(void* const* d_in, const int* in_sizes, int n_in,
                              void* d_out, int out_size) {
    const float*  xyz    = (const float*)d_in[0];
    const float*  tt     = (const float*)d_in[1];
    const float2* data   = (const float2*)d_in[2];
    const float*  bounds = (const float*)d_in[3];
    // d_in[4] (offsets) is the fixed 16x4 binary corner table -> hard-coded
    const float*  es     = (const float*)d_in[5];
    const int*    en     = (const int*)d_in[6];
    // d_in[7..9]: start_hash / start_frame / total_frame -> derived on device

    const int N = in_sizes[0] / 3;                        // xyz is [N,3]
    const int LF = out_size / N;                          // = L*f = 32
    const unsigned Tsz = (unsigned)(in_sizes[2] / LF);    // data is [L,T,f]
    const unsigned long long magic = 0xFFFFFFFFFFFFFFFFull / (unsigned long long)Tsz;

    const int total = N * 16;
    const int blocks = (total + 255) / 256;
    mh4d_kernel<<<blocks, 256>>>(xyz, tt, data, bounds, es, en,
                                 (float2*)d_out, N, Tsz, magic);
}

// round 13
// speedup vs baseline: 1.1351x; 1.1320x over previous
#include <cuda_runtime.h>
#include <cuda_bf16.h>

// MultiHashtable4d: 16-level 4D hash-grid encode.
//   out[n, l*2 + c] = sum_{16 corners} w_corner * data[l, index(corner), c]
//
// R13 layout: warp = (level l, 32 points), block = 128 threads = 4 levels
// x 32 points. Level constants and the hash/direct branch are warp-uniform.
// Gathers in 2 batches of 8 (regs down -> occupancy up). Output staged in
// padded smem and written fully coalesced. Table gathers use __ldcg.
//
// Bit-exactness vs the JAX reference:
//  * "+1" corner = trunc(fp32(f + 1.0f)) (can round up across an integer
//    boundary for large f) -- replicated exactly.
//  * divisions via __fdiv_rn (immune to fast-math flags).
// entrys_num dtype sniffed at runtime (int64 storage has zero hi-words).

#define LVL 16

__global__ void __launch_bounds__(128, 11) mh4d_kernel(
    const float* __restrict__ xyz,         // [N,3]
    const float* __restrict__ tt,          // [N,1]
    const float2* __restrict__ data,       // [L,T] of float2 (f=2)
    const float* __restrict__ bounds,      // [2,4]
    const float* __restrict__ es,          // [L,4] entrys_size (f32)
    const int*   __restrict__ en_raw,      // [L,4] entrys_num (i32 or i64 storage)
    float2* __restrict__ out,              // [N,L] of float2
    int N, unsigned Tsz, unsigned long long magic)
{
    __shared__ float  s_es[LVL * 4];
    __shared__ int    s_en[LVL * 4];
    __shared__ int    s_hash[LVL];
    __shared__ float  s_b0[4];
    __shared__ int    s_is64;
    __shared__ float2 s_out[4][33];        // [warp(level)][point], padded

    const int tid  = threadIdx.x;
    const int wid  = tid >> 5;
    const int lane = tid & 31;

    if (tid == 0) {
        // entrys_num[0] = [16,16,16,100]; int64 storage viewed as i32 has
        // zero odd words. Reads stay in-bounds for either layout.
        s_is64 = (en_raw[1] == 0 && en_raw[3] == 0 &&
                  en_raw[5] == 0 && en_raw[7] == 0) ? 1 : 0;
    }
    if (tid < LVL * 4) s_es[tid] = es[tid];
    if (tid < 4)       s_b0[tid] = bounds[tid];
    __syncthreads();
    if (tid < LVL * 4) s_en[tid] = s_is64 ? en_raw[2 * tid] : en_raw[tid];
    __syncthreads();
    if (tid == 0) {
        // first level with prod(entrys_num) > T starts hashing (prefix-OR
        // reproduces the reference's break semantics).
        int acc = 0;
        #pragma unroll
        for (int i = 0; i < LVL; i++) {
            long long p = (long long)s_en[4*i+0] * s_en[4*i+1]
                        * s_en[4*i+2] * s_en[4*i+3];
            acc |= (p > (long long)Tsz) ? 1 : 0;
            s_hash[i] = acc;
        }
    }
    __syncthreads();

    // block -> (point group, level group); warp -> one level, lane -> point
    const int pg = blockIdx.x >> 2;
    const int lg = blockIdx.x & 3;
    const int l  = lg * 4 + wid;           // warp-uniform
    int n = pg * 32 + lane;
    const bool valid = (n < N);
    if (n >= N) n = N - 1;                 // keep loads in-bounds, no early exit

    const float px = xyz[3 * n + 0];
    const float py = xyz[3 * n + 1];
    const float pz = xyz[3 * n + 2];
    // t -= start_frame/(total_frame-1); bounds[0][3]=start_frame/total_frame,
    // en[0][3]=total_frame -> shift = b0w*nt/(nt-1). (= 0 here.)
    const float nt = (float)s_en[3];
    const float pw = tt[n] - __fdiv_rn(s_b0[3] * nt, nt - 1.0f);

    // warp-uniform level constants
    const float es0 = s_es[4*l+0], es1 = s_es[4*l+1];
    const float es2 = s_es[4*l+2], es3 = s_es[4*l+3];
    const int   en0 = s_en[4*l+0], en1 = s_en[4*l+1];
    const int   en2 = s_en[4*l+2], en3 = s_en[4*l+3];
    const bool  ish = (s_hash[l] != 0);

    const float fx = __fdiv_rn(px - s_b0[0], es0);
    const float fy = __fdiv_rn(py - s_b0[1], es1);
    const float fz = __fdiv_rn(pz - s_b0[2], es2);
    const float fw = __fdiv_rn(pw - s_b0[3], es3);

    // low corner: trunc(f) (coords >= 0); high corner: trunc(fp32(f+1.0f))
    // (NOT low+1; fp32 add may round up across an integer boundary).
    const int bx = (int)fx, by = (int)fy, bz = (int)fz, bw = (int)fw;
    const int hx = (int)__fadd_rn(fx, 1.0f);
    const int hy = (int)__fadd_rn(fy, 1.0f);
    const int hz = (int)__fadd_rn(fz, 1.0f);
    const int hw = (int)__fadd_rn(fw, 1.0f);

    const float ox = fx - (float)bx;
    const float oy = fy - (float)by;
    const float oz = fz - (float)bz;
    const float ow = fw - (float)bw;

    int cxs[2], cys[2], czs[2], cws[2];
    cxs[0] = min(max(bx, 0), en0 - 1);  cxs[1] = min(max(hx, 0), en0 - 1);
    cys[0] = min(max(by, 0), en1 - 1);  cys[1] = min(max(hy, 0), en1 - 1);
    czs[0] = min(max(bz, 0), en2 - 1);  czs[1] = min(max(hz, 0), en2 - 1);
    cws[0] = min(max(bw, 0), en3 - 1);  cws[1] = min(max(hw, 0), en3 - 1);

    float wxs[2], wys[2], wzs[2], wws[2];
    wxs[0] = __saturatef(1.0f - ox); wxs[1] = __saturatef(ox);
    wys[0] = __saturatef(1.0f - oy); wys[1] = __saturatef(oy);
    wzs[0] = __saturatef(1.0f - oz); wzs[1] = __saturatef(oz);
    wws[0] = __saturatef(1.0f - ow); wws[1] = __saturatef(ow);

    // hoisted hash partials (6 u64 mults total instead of 48)
    const unsigned long long hy0 = (unsigned long long)(unsigned)cys[0] * 19349663ull;
    const unsigned long long hy1 = (unsigned long long)(unsigned)cys[1] * 19349663ull;
    const unsigned long long hz0 = (unsigned long long)(unsigned)czs[0] * 83492791ull;
    const unsigned long long hz1 = (unsigned long long)(unsigned)czs[1] * 83492791ull;
    const unsigned long long hw0 = (unsigned long long)(unsigned)cws[0] * 73856093ull;
    const unsigned long long hw1 = (unsigned long long)(unsigned)cws[1] * 73856093ull;

    const float2* tab = data + (size_t)Tsz * (unsigned)l;

    float acc0 = 0.0f, acc1 = 0.0f;

    // corner i = b*8 + j; bit3 (x) = b, bit2 (y) = j>>2, bit1 (z) = j>>1, bit0 (w) = j
    #pragma unroll
    for (int b = 0; b < 2; b++) {
        const unsigned long long hxp = (unsigned long long)(unsigned)cxs[b];
        const unsigned dxp = (unsigned)cxs[b] * (unsigned)en1;

        float2 vals[8];
        #pragma unroll
        for (int j = 0; j < 8; j++) {
            const int yb = (j >> 2) & 1, zb = (j >> 1) & 1, wb = j & 1;
            unsigned idx;
            if (ish) {                      // warp-uniform branch
                unsigned long long h = hxp ^ (yb ? hy1 : hy0)
                                           ^ (zb ? hz1 : hz0)
                                           ^ (wb ? hw1 : hw0);
                // Barrett: magic = floor((2^64-1)/Tsz); h < 2^38
                unsigned long long q = __umul64hi(h, magic);
                unsigned long long r = h - q * (unsigned long long)Tsz;
                if (r >= (unsigned long long)Tsz) r -= (unsigned long long)Tsz;
                if (r >= (unsigned long long)Tsz) r -= (unsigned long long)Tsz;
                idx = (unsigned)r;
            } else {                        // direct levels: prod <= T, fits u32
                unsigned d = dxp + (unsigned)cys[yb];
                d = d * (unsigned)en2 + (unsigned)czs[zb];
                d = d * (unsigned)en3 + (unsigned)cws[wb];
                idx = d;
            }
            vals[j] = __ldcg(&tab[idx]);    // L2-only: don't thrash L1
        }
        const float wx = wxs[b];
        #pragma unroll
        for (int j = 0; j < 8; j++) {
            const float w = wx * wys[(j >> 2) & 1]
                          * wzs[(j >> 1) & 1] * wws[j & 1];
            acc0 += w * vals[j].x;
            acc1 += w * vals[j].y;
        }
    }

    // stage result; remap to fully-coalesced, sector-dense stores
    s_out[wid][lane] = make_float2(acc0, acc1);
    __syncthreads();

    const int q = tid >> 2;                 // point within group (0..31)
    const int r = tid & 3;                  // level within block (0..3)
    const int nq = pg * 32 + q;
    if (nq < N && valid) {
        out[(size_t)nq * 16 + lg * 4 + r] = s_out[r][q];
    }
}

extern "C" void kernel_launch(void* const* d_in, const int* in_sizes, int n_in,
                              void* d_out, int out_size) {
    const float*  xyz    = (const float*)d_in[0];
    const float*  tt     = (const float*)d_in[1];
    const float2* data   = (const float2*)d_in[2];
    const float*  bounds = (const float*)d_in[3];
    // d_in[4] (offsets) is the fixed 16x4 binary corner table -> hard-coded
    const float*  es     = (const float*)d_in[5];
    const int*    en     = (const int*)d_in[6];
    // d_in[7..9]: start_hash / start_frame / total_frame -> derived on device

    const int N = in_sizes[0] / 3;                        // xyz is [N,3]
    const int LF = out_size / N;                          // = L*f = 32
    const unsigned Tsz = (unsigned)(in_sizes[2] / LF);    // data is [L,T,f]
    const unsigned long long magic = 0xFFFFFFFFFFFFFFFFull / (unsigned long long)Tsz;

    const int pgroups = (N + 31) / 32;
    const int blocks = pgroups * 4;        // 4 level-groups of 4 levels each
    mh4d_kernel<<<blocks, 128>>>(xyz, tt, data, bounds, es, en,
                                 (float2*)d_out, N, Tsz, magic);
}